// round 10
// baseline (speedup 1.0000x reference)
#include <cuda_runtime.h>
#include <cuda_fp16.h>
#include <mma.h>
#include <math.h>

using namespace nvcuda;

#define H_DIM   4096
#define BATCH   64
#define T_STEPS 128
#define I_DIM   1024
#define NNZ_IH  131072
#define NNZ_HH  262144

#define ROWS_PER_BLK 8

// ---------------- scratch (device globals; no runtime allocation) ----------------
__device__ __half g_x16[(size_t)T_STEPS * I_DIM * BATCH];   // x as (T, I, B) fp16
__device__ __half g_pre[(size_t)T_STEPS * H_DIM * BATCH];   // W_ih x_t (no bias), fp16
__device__ __half g_h16[2][H_DIM * BATCH];                  // h ping-pong (H, B) fp16
__device__ float  g_W32[(size_t)H_DIM * I_DIM];             // dense W_ih fp32 accum
__device__ __half g_W16[(size_t)H_DIM * I_DIM];             // dense W_ih fp16
__device__ int    g_hh_ptr[H_DIM + 1];
__device__ int2   g_hh_pk[NNZ_HH];     // (col, val fp32 bits)
__device__ int    g_cnt[H_DIM];

// ---------------- setup kernels ----------------
__global__ void k_zero_all() {
    int idx = blockIdx.x * blockDim.x + threadIdx.x;
    if (idx < H_DIM * BATCH) g_h16[0][idx] = __float2half(0.0f);
    if (idx < H_DIM)         g_cnt[idx]   = 0;
}

__global__ void k_zero_cnt() {
    int idx = blockIdx.x * blockDim.x + threadIdx.x;
    if (idx < H_DIM) g_cnt[idx] = 0;
}

__global__ void k_zero_w() {
    size_t idx = (size_t)blockIdx.x * blockDim.x + threadIdx.x;
    size_t n4  = (size_t)H_DIM * I_DIM / 4;
    if (idx < n4) ((float4*)g_W32)[idx] = make_float4(0.f, 0.f, 0.f, 0.f);
}

__global__ void k_fill_w(const int* __restrict__ ih_rows, const int* __restrict__ ih_cols,
                         const float* __restrict__ ih_vals) {
    int k = blockIdx.x * blockDim.x + threadIdx.x;
    if (k < NNZ_IH)
        atomicAdd(&g_W32[(size_t)ih_rows[k] * I_DIM + ih_cols[k]], ih_vals[k]);
}

__global__ void k_cvt_w() {
    size_t idx = (size_t)blockIdx.x * blockDim.x + threadIdx.x;
    size_t n2  = (size_t)H_DIM * I_DIM / 2;
    if (idx < n2) {
        float2 v = ((const float2*)g_W32)[idx];
        ((__half2*)g_W16)[idx] = __floats2half2_rn(v.x, v.y);
    }
}

__global__ void k_hist(const int* __restrict__ hh_rows) {
    int k = blockIdx.x * blockDim.x + threadIdx.x;
    if (k < NNZ_HH) atomicAdd(&g_cnt[hh_rows[k]], 1);
}

// exclusive scan of 4096 counts -> row pointers (one block)
__global__ void k_scan() {
    __shared__ int sums[1024];
    int tid  = threadIdx.x;
    int base = tid * 4;
    int v0 = g_cnt[base + 0];
    int v1 = g_cnt[base + 1];
    int v2 = g_cnt[base + 2];
    int v3 = g_cnt[base + 3];
    int local = v0 + v1 + v2 + v3;
    sums[tid] = local;
    __syncthreads();
    for (int off = 1; off < 1024; off <<= 1) {
        int t = (tid >= off) ? sums[tid - off] : 0;
        __syncthreads();
        sums[tid] += t;
        __syncthreads();
    }
    int excl = sums[tid] - local;
    g_hh_ptr[base + 0] = excl;
    g_hh_ptr[base + 1] = excl + v0;
    g_hh_ptr[base + 2] = excl + v0 + v1;
    g_hh_ptr[base + 3] = excl + v0 + v1 + v2;
    if (tid == 1023) g_hh_ptr[H_DIM] = sums[1023];
}

__global__ void k_scatter(const int* __restrict__ hh_rows, const int* __restrict__ hh_cols,
                          const float* __restrict__ hh_vals) {
    int k = blockIdx.x * blockDim.x + threadIdx.x;
    if (k < NNZ_HH) {
        int r = hh_rows[k];
        int p = g_hh_ptr[r] + atomicAdd(&g_cnt[r], 1);
        g_hh_pk[p] = make_int2(hh_cols[k], __float_as_int(hh_vals[k]));
    }
}

// x (B,T,I) fp32 -> g_x16 (T,I,B) fp16
__global__ void k_transpose_x(const float* __restrict__ x) {
    __shared__ float tile[32][33];
    int t  = blockIdx.z;
    int i0 = blockIdx.x * 32;
    int b0 = blockIdx.y * 32;
    int b = b0 + threadIdx.y;
    int i = i0 + threadIdx.x;
    tile[threadIdx.y][threadIdx.x] = x[((size_t)b * T_STEPS + t) * I_DIM + i];
    __syncthreads();
    int iw = i0 + threadIdx.y;
    int bw = b0 + threadIdx.x;
    g_x16[((size_t)t * I_DIM + iw) * BATCH + bw] =
        __float2half(tile[threadIdx.x][threadIdx.y]);
}

// ---------------- pre GEMM: pre[t] = W_ih (dense fp16) @ x_t, tensor cores ----------------
// grid (H/128, T/2). block 512 = 16 warps in 4x4 arrangement; each warp a 32x32
// tile (2x2 wmma frags, fp32 accum). Block tile: 128 rows x (2 timesteps x 64 b).
__global__ void __launch_bounds__(512)
k_gemm_pre() {
    extern __shared__ float gbuf[];              // 16 warps x 32x32 fp32 = 64KB
    int w    = threadIdx.x >> 5;
    int lane = threadIdx.x & 31;
    int wm   = w >> 2;                           // 0..3
    int wn   = w & 3;                            // 0..3
    int row0 = blockIdx.x * 128 + wm * 32;
    int t    = 2 * blockIdx.y + (wn >> 1);
    int b0   = (wn & 1) * 32;

    const __half* __restrict__ A  = g_W16 + (size_t)row0 * I_DIM;
    const __half* __restrict__ Bx = g_x16 + (size_t)t * I_DIM * BATCH + b0;

    wmma::fragment<wmma::accumulator, 16, 16, 16, float> c[2][2];
    #pragma unroll
    for (int i = 0; i < 2; i++)
        #pragma unroll
        for (int j = 0; j < 2; j++)
            wmma::fill_fragment(c[i][j], 0.0f);

    for (int k0 = 0; k0 < I_DIM; k0 += 16) {
        wmma::fragment<wmma::matrix_a, 16, 16, 16, __half, wmma::row_major> a[2];
        wmma::fragment<wmma::matrix_b, 16, 16, 16, __half, wmma::row_major> b[2];
        wmma::load_matrix_sync(a[0], A + k0, I_DIM);
        wmma::load_matrix_sync(a[1], A + 16 * I_DIM + k0, I_DIM);
        wmma::load_matrix_sync(b[0], Bx + (size_t)k0 * BATCH, BATCH);
        wmma::load_matrix_sync(b[1], Bx + (size_t)k0 * BATCH + 16, BATCH);
        #pragma unroll
        for (int i = 0; i < 2; i++)
            #pragma unroll
            for (int j = 0; j < 2; j++)
                wmma::mma_sync(c[i][j], a[i], b[j], c[i][j]);
    }

    // per-warp: fp32 accum -> smem -> fp16 pre
    float* buf = gbuf + w * 1024;                // 32x32, ld 32
    #pragma unroll
    for (int i = 0; i < 2; i++)
        #pragma unroll
        for (int j = 0; j < 2; j++)
            wmma::store_matrix_sync(buf + i * 16 * 32 + j * 16, c[i][j], 32,
                                    wmma::mem_row_major);
    __syncwarp();

    __half2* dst = (__half2*)(g_pre + (size_t)t * H_DIM * BATCH);
    #pragma unroll
    for (int it = 0; it < 16; it++) {
        int idx = it * 32 + lane;                // 0..511 half2 units
        int rr  = idx >> 4;                      // 0..31
        int c2  = idx & 15;                      // 0..15
        float2 v = ((const float2*)(buf + rr * 32))[c2];
        dst[(size_t)(row0 + rr) * (BATCH / 2) + (b0 >> 1) + c2] =
            __floats2half2_rn(v.x, v.y);
    }
}

// ---------------- per-timestep kernel (hh only; R7-proven) ----------------
// block (32,16): each row served by a warp PAIR (k-split) -> 8192 warps chip-wide.
__global__ void __launch_bounds__(512)
k_step(const float* __restrict__ bias, float* __restrict__ out, int t, int prev) {
    int lane = threadIdx.x;
    int ty   = threadIdx.y;            // 0..15
    int ry   = ty & 7;
    int half = ty >> 3;
    int r    = blockIdx.x * ROWS_PER_BLK + ry;

    const __half2* __restrict__ hb = (const __half2*)g_h16[prev];

    int k0 = g_hh_ptr[r];
    int k1 = g_hh_ptr[r + 1];
    int mid = (k0 + k1 + 1) >> 1;
    int ka = half ? mid : k0;
    int kb = half ? k1  : mid;

    float ax = 0.0f, ay = 0.0f;
    #pragma unroll 4
    for (int k = ka; k < kb; k++) {
        int2 w = g_hh_pk[k];
        float v = __int_as_float(w.y);
        float2 f = __half22float2(hb[w.x * (BATCH / 2) + lane]);
        ax += v * f.x;
        ay += v * f.y;
    }

    __shared__ float2 part[ROWS_PER_BLK][32];
    __shared__ float  tile[ROWS_PER_BLK][BATCH + 1];

    if (half == 1) part[ry][lane] = make_float2(ax, ay);
    __syncthreads();

    if (half == 0) {
        float2 p = part[ry][lane];
        float bv = bias[r];
        float2 pre = __half22float2(
            ((const __half2*)(g_pre + (size_t)t * H_DIM * BATCH))
                [r * (BATCH / 2) + lane]);
        float hx = tanhf(bv + pre.x + ax + p.x);
        float hy = tanhf(bv + pre.y + ay + p.y);

        ((__half2*)g_h16[prev ^ 1])[r * (BATCH / 2) + lane] =
            __floats2half2_rn(hx, hy);

        tile[ry][2 * lane]     = hx;
        tile[ry][2 * lane + 1] = hy;
    }
    __syncthreads();

    // out (B,T,H) fp32, coalesced: 512 threads cover 512 elements
    int idx = ty * 32 + lane;
    int b   = idx >> 3;
    int rr  = idx & 7;
    out[((size_t)b * T_STEPS + t) * H_DIM + blockIdx.x * ROWS_PER_BLK + rr] =
        tile[rr][b];
}

// ---------------- launch ----------------
extern "C" void kernel_launch(void* const* d_in, const int* in_sizes, int n_in,
                              void* d_out, int out_size) {
    const float* x       = (const float*)d_in[0];
    const float* ih_vals = (const float*)d_in[1];
    const float* hh_vals = (const float*)d_in[2];
    const float* hh_bias = (const float*)d_in[3];
    const int*   ih_rows = (const int*)  d_in[4];
    const int*   ih_cols = (const int*)  d_in[5];
    const int*   hh_rows = (const int*)  d_in[6];
    const int*   hh_cols = (const int*)  d_in[7];
    float* out = (float*)d_out;

    static int smem_set = 0;
    const int GEMM_SMEM = 16 * 32 * 32 * (int)sizeof(float);   // 64KB
    if (!smem_set) {
        cudaFuncSetAttribute(k_gemm_pre, cudaFuncAttributeMaxDynamicSharedMemorySize,
                             GEMM_SMEM);
        smem_set = 1;
    }

    // ---- setup: hh CSR + dense W_ih + x transpose ----
    k_zero_all<<<(H_DIM * BATCH + 255) / 256, 256>>>();
    k_hist<<<(NNZ_HH + 255) / 256, 256>>>(hh_rows);
    k_scan<<<1, 1024>>>();
    k_zero_cnt<<<(H_DIM + 255) / 256, 256>>>();
    k_scatter<<<(NNZ_HH + 255) / 256, 256>>>(hh_rows, hh_cols, hh_vals);

    k_zero_w<<<(H_DIM * I_DIM / 4 + 255) / 256, 256>>>();
    k_fill_w<<<(NNZ_IH + 255) / 256, 256>>>(ih_rows, ih_cols, ih_vals);
    k_cvt_w<<<(H_DIM * I_DIM / 2 + 255) / 256, 256>>>();

    k_transpose_x<<<dim3(I_DIM / 32, BATCH / 32, T_STEPS), dim3(32, 32)>>>(x);

    // ---- ih term for all t via tensor cores ----
    k_gemm_pre<<<dim3(H_DIM / 128, T_STEPS / 2), 512, GEMM_SMEM>>>();

    // ---- sequential recurrence: hh gathers only ----
    for (int t = 0; t < T_STEPS; t++) {
        k_step<<<H_DIM / ROWS_PER_BLK, dim3(32, 16)>>>(hh_bias, out, t, t & 1);
    }
}

// round 11
// speedup vs baseline: 1.5147x; 1.5147x over previous
#include <cuda_runtime.h>
#include <cuda_fp16.h>
#include <mma.h>
#include <math.h>

using namespace nvcuda;

#define H_DIM   4096
#define BATCH   64
#define T_STEPS 128
#define I_DIM   1024
#define NNZ_IH  131072
#define NNZ_HH  262144

#define ROWS_PER_BLK 8

// ---------------- scratch (device globals; no runtime allocation) ----------------
__device__ __half g_x16[(size_t)T_STEPS * I_DIM * BATCH];   // x as (T, I, B) fp16
__device__ __half g_pre[(size_t)T_STEPS * H_DIM * BATCH];   // W_ih x_t (no bias), fp16
__device__ __half g_h16[2][H_DIM * BATCH];                  // h ping-pong (H, B) fp16
__device__ float  g_W32[(size_t)H_DIM * I_DIM];             // dense W_ih fp32 accum
__device__ __half g_W16[(size_t)H_DIM * I_DIM];             // dense W_ih fp16
__device__ int    g_hh_ptr[H_DIM + 1];
__device__ unsigned g_hh_pkc[NNZ_HH];  // packed: low16 = col, high16 = fp16 val bits
__device__ int    g_cnt[H_DIM];

// ---------------- setup kernels ----------------
__global__ void k_zero_all() {
    int idx = blockIdx.x * blockDim.x + threadIdx.x;
    if (idx < H_DIM * BATCH) g_h16[0][idx] = __float2half(0.0f);
    if (idx < H_DIM)         g_cnt[idx]   = 0;
}

__global__ void k_zero_cnt() {
    int idx = blockIdx.x * blockDim.x + threadIdx.x;
    if (idx < H_DIM) g_cnt[idx] = 0;
}

__global__ void k_zero_w() {
    size_t idx = (size_t)blockIdx.x * blockDim.x + threadIdx.x;
    size_t n4  = (size_t)H_DIM * I_DIM / 4;
    if (idx < n4) ((float4*)g_W32)[idx] = make_float4(0.f, 0.f, 0.f, 0.f);
}

__global__ void k_fill_w(const int* __restrict__ ih_rows, const int* __restrict__ ih_cols,
                         const float* __restrict__ ih_vals) {
    int k = blockIdx.x * blockDim.x + threadIdx.x;
    if (k < NNZ_IH)
        atomicAdd(&g_W32[(size_t)ih_rows[k] * I_DIM + ih_cols[k]], ih_vals[k]);
}

__global__ void k_cvt_w() {
    size_t idx = (size_t)blockIdx.x * blockDim.x + threadIdx.x;
    size_t n2  = (size_t)H_DIM * I_DIM / 2;
    if (idx < n2) {
        float2 v = ((const float2*)g_W32)[idx];
        ((__half2*)g_W16)[idx] = __floats2half2_rn(v.x, v.y);
    }
}

__global__ void k_hist(const int* __restrict__ hh_rows) {
    int k = blockIdx.x * blockDim.x + threadIdx.x;
    if (k < NNZ_HH) atomicAdd(&g_cnt[hh_rows[k]], 1);
}

// exclusive scan of 4096 counts -> row pointers (one block)
__global__ void k_scan() {
    __shared__ int sums[1024];
    int tid  = threadIdx.x;
    int base = tid * 4;
    int v0 = g_cnt[base + 0];
    int v1 = g_cnt[base + 1];
    int v2 = g_cnt[base + 2];
    int v3 = g_cnt[base + 3];
    int local = v0 + v1 + v2 + v3;
    sums[tid] = local;
    __syncthreads();
    for (int off = 1; off < 1024; off <<= 1) {
        int t = (tid >= off) ? sums[tid - off] : 0;
        __syncthreads();
        sums[tid] += t;
        __syncthreads();
    }
    int excl = sums[tid] - local;
    g_hh_ptr[base + 0] = excl;
    g_hh_ptr[base + 1] = excl + v0;
    g_hh_ptr[base + 2] = excl + v0 + v1;
    g_hh_ptr[base + 3] = excl + v0 + v1 + v2;
    if (tid == 1023) g_hh_ptr[H_DIM] = sums[1023];
}

__global__ void k_scatter(const int* __restrict__ hh_rows, const int* __restrict__ hh_cols,
                          const float* __restrict__ hh_vals) {
    int k = blockIdx.x * blockDim.x + threadIdx.x;
    if (k < NNZ_HH) {
        int r = hh_rows[k];
        int p = g_hh_ptr[r] + atomicAdd(&g_cnt[r], 1);
        unsigned hv = (unsigned)__half_as_ushort(__float2half(hh_vals[k]));
        g_hh_pkc[p] = (unsigned)hh_cols[k] | (hv << 16);
    }
}

// x (B,T,I) fp32 -> g_x16 (T,I,B) fp16
__global__ void k_transpose_x(const float* __restrict__ x) {
    __shared__ float tile[32][33];
    int t  = blockIdx.z;
    int i0 = blockIdx.x * 32;
    int b0 = blockIdx.y * 32;
    int b = b0 + threadIdx.y;
    int i = i0 + threadIdx.x;
    tile[threadIdx.y][threadIdx.x] = x[((size_t)b * T_STEPS + t) * I_DIM + i];
    __syncthreads();
    int iw = i0 + threadIdx.y;
    int bw = b0 + threadIdx.x;
    g_x16[((size_t)t * I_DIM + iw) * BATCH + bw] =
        __float2half(tile[threadIdx.x][threadIdx.y]);
}

// ---------------- pre GEMM: smem-staged wmma ----------------
// C[4096, T*64] = W16[4096,1024] @ X[1024, T*64].
// Block tile 128x128 (128 rows x 2 timesteps), k-chunk 64, 8 warps (4x2),
// warp tile 32x64 (2x4 wmma 16x16x16 frags, fp32 accum).
#define A_LD 72    // 64 + 8 pad halves (row = 144B, 16B-aligned)
#define B_LD 136   // 128 + 8 pad halves (row = 272B, 16B-aligned)
#define GEMM_SMEM 65536

__global__ void __launch_bounds__(256)
k_gemm_pre() {
    extern __shared__ char smbase[];
    __half* Asm = (__half*)smbase;                    // [128][A_LD] = 18432B
    __half* Bsm = (__half*)(smbase + 18432);          // [64][B_LD]  = 17408B
    float*  fbuf = (float*)smbase;                    // epilogue: 8 warps x 32x64

    int tid  = threadIdx.x;
    int w    = tid >> 5;
    int lane = tid & 31;
    int wm   = w >> 1;                                // 0..3
    int wn   = w & 1;                                 // 0..1
    int row0 = blockIdx.x * 128;
    int t0   = blockIdx.y * 2;

    wmma::fragment<wmma::accumulator, 16, 16, 16, float> c[2][4];
    #pragma unroll
    for (int i = 0; i < 2; i++)
        #pragma unroll
        for (int j = 0; j < 4; j++)
            wmma::fill_fragment(c[i][j], 0.0f);

    for (int k0 = 0; k0 < I_DIM; k0 += 64) {
        // stage A chunk: 128 rows x 64 halves (coalesced float4)
        #pragma unroll
        for (int p = 0; p < 4; p++) {
            int i   = tid + p * 256;                  // 0..1023
            int row = i >> 3;
            int seg = i & 7;
            *(float4*)(&Asm[row * A_LD + seg * 8]) =
                *(const float4*)(g_W16 + (size_t)(row0 + row) * I_DIM + k0 + seg * 8);
        }
        // stage B chunk: 64 k x 128 n  (n = tt*64 + b)
        #pragma unroll
        for (int p = 0; p < 4; p++) {
            int i    = tid + p * 256;                 // 0..1023
            int k    = i >> 4;
            int rest = i & 15;
            int tt   = rest >> 3;
            int seg  = rest & 7;
            *(float4*)(&Bsm[k * B_LD + tt * 64 + seg * 8]) =
                *(const float4*)(g_x16 + (size_t)(t0 + tt) * I_DIM * BATCH
                                 + (size_t)(k0 + k) * BATCH + seg * 8);
        }
        __syncthreads();

        #pragma unroll
        for (int kk = 0; kk < 4; kk++) {
            wmma::fragment<wmma::matrix_a, 16, 16, 16, __half, wmma::row_major> a[2];
            wmma::fragment<wmma::matrix_b, 16, 16, 16, __half, wmma::row_major> b[4];
            wmma::load_matrix_sync(a[0], &Asm[(wm * 32) * A_LD + kk * 16], A_LD);
            wmma::load_matrix_sync(a[1], &Asm[(wm * 32 + 16) * A_LD + kk * 16], A_LD);
            #pragma unroll
            for (int j = 0; j < 4; j++)
                wmma::load_matrix_sync(b[j], &Bsm[(kk * 16) * B_LD + wn * 64 + j * 16], B_LD);
            #pragma unroll
            for (int i = 0; i < 2; i++)
                #pragma unroll
                for (int j = 0; j < 4; j++)
                    wmma::mma_sync(c[i][j], a[i], b[j], c[i][j]);
        }
        __syncthreads();
    }

    // epilogue: fp32 accum -> smem -> fp16 pre[t0+wn]
    float* buf = fbuf + w * 2048;                     // 32x64
    #pragma unroll
    for (int i = 0; i < 2; i++)
        #pragma unroll
        for (int j = 0; j < 4; j++)
            wmma::store_matrix_sync(buf + i * 16 * 64 + j * 16, c[i][j], 64,
                                    wmma::mem_row_major);
    __syncwarp();

    __half2* dst = (__half2*)(g_pre + (size_t)(t0 + wn) * H_DIM * BATCH);
    #pragma unroll
    for (int rr = 0; rr < 32; rr++) {
        float2 v = ((const float2*)(buf + rr * 64))[lane];
        dst[(size_t)(row0 + wm * 32 + rr) * (BATCH / 2) + lane] =
            __floats2half2_rn(v.x, v.y);
    }
}

// ---------------- per-timestep kernel (hh only; R7-proven, 4B weights) ----------------
// block (32,16): each row served by a warp PAIR (k-split) -> 8192 warps chip-wide.
__global__ void __launch_bounds__(512)
k_step(const float* __restrict__ bias, float* __restrict__ out, int t, int prev) {
    int lane = threadIdx.x;
    int ty   = threadIdx.y;            // 0..15
    int ry   = ty & 7;
    int half = ty >> 3;
    int r    = blockIdx.x * ROWS_PER_BLK + ry;

    const __half2* __restrict__ hb = (const __half2*)g_h16[prev];

    int k0 = g_hh_ptr[r];
    int k1 = g_hh_ptr[r + 1];
    int mid = (k0 + k1 + 1) >> 1;
    int ka = half ? mid : k0;
    int kb = half ? k1  : mid;

    float ax = 0.0f, ay = 0.0f;
    #pragma unroll 4
    for (int k = ka; k < kb; k++) {
        unsigned w = g_hh_pkc[k];
        float v = __half2float(__ushort_as_half((unsigned short)(w >> 16)));
        float2 f = __half22float2(hb[(w & 0xFFFFu) * (BATCH / 2) + lane]);
        ax += v * f.x;
        ay += v * f.y;
    }

    __shared__ float2 part[ROWS_PER_BLK][32];
    __shared__ float  tile[ROWS_PER_BLK][BATCH + 1];

    if (half == 1) part[ry][lane] = make_float2(ax, ay);
    __syncthreads();

    if (half == 0) {
        float2 p = part[ry][lane];
        float bv = bias[r];
        float2 pre = __half22float2(
            ((const __half2*)(g_pre + (size_t)t * H_DIM * BATCH))
                [r * (BATCH / 2) + lane]);
        float hx = tanhf(bv + pre.x + ax + p.x);
        float hy = tanhf(bv + pre.y + ay + p.y);

        ((__half2*)g_h16[prev ^ 1])[r * (BATCH / 2) + lane] =
            __floats2half2_rn(hx, hy);

        tile[ry][2 * lane]     = hx;
        tile[ry][2 * lane + 1] = hy;
    }
    __syncthreads();

    // out (B,T,H) fp32, coalesced: 512 threads cover 512 elements
    int idx = ty * 32 + lane;
    int b   = idx >> 3;
    int rr  = idx & 7;
    out[((size_t)b * T_STEPS + t) * H_DIM + blockIdx.x * ROWS_PER_BLK + rr] =
        tile[rr][b];
}

// ---------------- launch ----------------
extern "C" void kernel_launch(void* const* d_in, const int* in_sizes, int n_in,
                              void* d_out, int out_size) {
    const float* x       = (const float*)d_in[0];
    const float* ih_vals = (const float*)d_in[1];
    const float* hh_vals = (const float*)d_in[2];
    const float* hh_bias = (const float*)d_in[3];
    const int*   ih_rows = (const int*)  d_in[4];
    const int*   ih_cols = (const int*)  d_in[5];
    const int*   hh_rows = (const int*)  d_in[6];
    const int*   hh_cols = (const int*)  d_in[7];
    float* out = (float*)d_out;

    static int smem_set = 0;
    if (!smem_set) {
        cudaFuncSetAttribute(k_gemm_pre, cudaFuncAttributeMaxDynamicSharedMemorySize,
                             GEMM_SMEM);
        smem_set = 1;
    }

    // ---- setup: hh CSR (packed) + dense W_ih + x transpose ----
    k_zero_all<<<(H_DIM * BATCH + 255) / 256, 256>>>();
    k_hist<<<(NNZ_HH + 255) / 256, 256>>>(hh_rows);
    k_scan<<<1, 1024>>>();
    k_zero_cnt<<<(H_DIM + 255) / 256, 256>>>();
    k_scatter<<<(NNZ_HH + 255) / 256, 256>>>(hh_rows, hh_cols, hh_vals);

    k_zero_w<<<(H_DIM * I_DIM / 4 + 255) / 256, 256>>>();
    k_fill_w<<<(NNZ_IH + 255) / 256, 256>>>(ih_rows, ih_cols, ih_vals);
    k_cvt_w<<<(H_DIM * I_DIM / 2 + 255) / 256, 256>>>();

    k_transpose_x<<<dim3(I_DIM / 32, BATCH / 32, T_STEPS), dim3(32, 32)>>>(x);

    // ---- ih term for all t via tensor cores (smem-staged) ----
    k_gemm_pre<<<dim3(H_DIM / 128, T_STEPS / 2), 256, GEMM_SMEM>>>();

    // ---- sequential recurrence: hh gathers only ----
    for (int t = 0; t < T_STEPS; t++) {
        k_step<<<H_DIM / ROWS_PER_BLK, dim3(32, 16)>>>(hh_bias, out, t, t & 1);
    }
}